// round 5
// baseline (speedup 1.0000x reference)
#include <cuda_runtime.h>

namespace {
constexpr int PNP = 4;
constexpr int MOD = 4;
constexpr int NCH = 100;
constexpr int F   = NCH + PNP;       // 104
constexpr int FM  = F * MOD;         // 416
constexpr int XW  = PNP * (1 + MOD); // 20
constexpr int NT  = 128;
constexpr int QSTR = F;              // mode-row stride in Qt (416B, 16B-aligned)
constexpr int QSZ  = MOD * QSTR;     // 416 floats per Q buffer
constexpr float C0F   = 299792458.0f;
constexpr float ALPHA = 2.3025850929940457e-4f;
}

using ull = unsigned long long;

__device__ __forceinline__ ull pk2(float a, float b) {
    ull r; asm("mov.b64 %0,{%1,%2};" : "=l"(r) : "f"(a), "f"(b)); return r;
}
__device__ __forceinline__ void fma2(ull& d, ull a, ull b) {
    asm("fma.rn.f32x2 %0,%1,%2,%0;" : "+l"(d) : "l"(a), "l"(b));
}
__device__ __forceinline__ float up2sum(ull v) {
    float lo, hi; asm("mov.b64 {%0,%1},%2;" : "=f"(lo), "=f"(hi) : "l"(v));
    return lo + hi;
}

__global__ __launch_bounds__(NT, 4) void raman_kernel(
    const float* __restrict__ x,
    const float* __restrict__ sig_freq,
    const float* __restrict__ sig_pow,
    const float* __restrict__ sig_loss,
    const float* __restrict__ lcoef,
    const float* __restrict__ overlap,
    const float* __restrict__ raman,
    const int*   __restrict__ steps_p,
    const float* __restrict__ length_p,
    const float* __restrict__ maxf_p,
    int Lr,
    float* __restrict__ out)
{
    extern __shared__ float sm[];
    float* gT    = sm;               // F*F (init staging; gain then lives in regs)
    float* Qt    = gT + F * F;       // 2 * QSZ, mode-major Qt[m*QSTR + j], dbl-buffered
    float* PcS   = Qt + 2 * QSZ;     // FM
    float* lossS = PcS + FM;         // FM
    float* accS  = lossS + FM;       // FM (RK accumulator)
    float* ovS   = accS + FM;        // 16 (row-major overlap)
    float* frq   = ovS + 16;         // F

    const int b = blockIdx.x;
    const int t = threadIdx.x;
    const float* xb = x + b * XW;

    const int   steps  = *steps_p;
    const float length = *length_p;
    const float maxf   = *maxf_p;
    const float h  = length / (float)(steps - 1);
    const float h2 = 0.5f * h;
    const float h6 = h * (1.0f / 6.0f);

    if (t < 16) ovS[t] = overlap[t];
    for (int u = t; u < F; u += NT)
        frq[u] = (u < PNP) ? (C0F / xb[u]) : sig_freq[u - PNP];
    const float lc0 = lcoef[0], lc1 = lcoef[1], lc2 = lcoef[2];
    for (int u = t; u < FM; u += NT) {
        float lv, pv;
        if (u < PNP * MOD) {
            const float wn = xb[u >> 2] * 1e9f;
            lv = (lc2 + lc1 * wn + lc0 * wn * wn) * ALPHA;
            pv = xb[PNP + u];
        } else {
            lv = sig_loss[u - PNP * MOD];
            pv = sig_pow[u - PNP * MOD];
        }
        lossS[u] = lv; PcS[u] = pv;
    }
    __syncthreads();

    // ---- per-batch gain matrix (staged in smem, then -> regs) ----
    {
        const float scale = (float)(Lr - 1) / maxf;
        for (int idx = t; idx < F * F; idx += NT) {
            const int ii = idx / F;
            const int jj = idx - ii * F;
            const float fi = frq[ii], fj = frq[jj];
            const float fd = fj - fi;
            const float pos = fabsf(fd) * scale;
            int i0 = (int)floorf(pos);
            i0 = min(max(i0, 0), Lr - 2);
            const float w = pos - (float)i0;
            float g = raman[i0] * (1.0f - w) + raman[i0 + 1] * w;
            if (fd < 0.0f) g = -g;
            g *= fmaxf(1.0f, fi / fj);
            gT[idx] = g;
        }
    }
    __syncthreads();

    const int  i     = t;
    const bool rowok = (i < F);

    // packed gain pairs {g[2k], g[2k+1]} — loaded once, naturally paired
    ull gp[F / 2];
    float pk0 = 0.f, pk1 = 0.f, pkv2 = 0.f, pk3 = 0.f;
    if (rowok) {
        #pragma unroll
        for (int k = 0; k < F / 2; ++k)
            gp[k] = *(const ull*)(gT + i * F + 2 * k);
        const float4 p0 = *(const float4*)(PcS + 4 * i);
        pk0 = p0.x; pk1 = p0.y; pkv2 = p0.z; pk3 = p0.w;
        // prologue: Q(P0) into buffer 0
        const ull a01 = pk2(pk0, pk1), a23 = pk2(pkv2, pk3);
        #pragma unroll
        for (int m = 0; m < 4; ++m) {
            const ulonglong2 o = ((const ulonglong2*)ovS)[m];
            ull tq = 0; fma2(tq, o.x, a01); fma2(tq, o.y, a23);
            Qt[m * QSTR + i] = up2sum(tq);
        }
    }
    __syncthreads();

    const int nst = 4 * (steps - 1);
    int cur = 0;

    for (int it = 0; it < nst; ++it) {
        const int s4 = it & 3;
        if (rowok) {
            // ---- matvec: A[m] = sum_j gain[j] * Q[m][j] ----
            ull a0 = 0, a1 = 0, a2 = 0, a3 = 0;
            const float* Qc = Qt + cur * QSZ;
            #pragma unroll
            for (int j4 = 0; j4 < F; j4 += 4) {
                const int k = j4 >> 1;
                const ulonglong2 q0 = *(const ulonglong2*)(Qc + 0 * QSTR + j4);
                const ulonglong2 q1 = *(const ulonglong2*)(Qc + 1 * QSTR + j4);
                const ulonglong2 q2 = *(const ulonglong2*)(Qc + 2 * QSTR + j4);
                const ulonglong2 q3 = *(const ulonglong2*)(Qc + 3 * QSTR + j4);
                fma2(a0, gp[k], q0.x); fma2(a0, gp[k + 1], q0.y);
                fma2(a1, gp[k], q1.x); fma2(a1, gp[k + 1], q1.y);
                fma2(a2, gp[k], q2.x); fma2(a2, gp[k + 1], q2.y);
                fma2(a3, gp[k], q3.x); fma2(a3, gp[k + 1], q3.y);
            }
            const float A0 = up2sum(a0), A1 = up2sum(a1);
            const float A2 = up2sum(a2), A3 = up2sum(a3);

            const float4 lv = *(const float4*)(lossS + 4 * i);
            const float4 pc = *(const float4*)(PcS + 4 * i);
            const float k0 = (A0 - lv.x) * pk0;
            const float k1 = (A1 - lv.y) * pk1;
            const float k2 = (A2 - lv.z) * pkv2;
            const float k3 = (A3 - lv.w) * pk3;

            float4 av;
            if (s4 == 0) {
                av = make_float4(k0, k1, k2, k3);
            } else {
                av = *(const float4*)(accS + 4 * i);
                const float c = (s4 == 3) ? 1.0f : 2.0f;
                av.x = fmaf(c, k0, av.x); av.y = fmaf(c, k1, av.y);
                av.z = fmaf(c, k2, av.z); av.w = fmaf(c, k3, av.w);
            }
            if (s4 < 3) {
                *(float4*)(accS + 4 * i) = av;
                const float cs = (s4 == 2) ? h : h2;
                pk0 = fmaf(cs, k0, pc.x);
                pk1 = fmaf(cs, k1, pc.y);
                pkv2 = fmaf(cs, k2, pc.z);
                pk3 = fmaf(cs, k3, pc.w);
            } else {
                pk0 = fmaf(h6, av.x, pc.x);
                pk1 = fmaf(h6, av.y, pc.y);
                pkv2 = fmaf(h6, av.z, pc.z);
                pk3 = fmaf(h6, av.w, pc.w);
                *(float4*)(PcS + 4 * i) = make_float4(pk0, pk1, pkv2, pk3);
            }

            // ---- Q for next stage into alternate buffer ----
            const ull p01 = pk2(pk0, pk1), p23 = pk2(pkv2, pk3);
            float* Qn = Qt + (cur ^ 1) * QSZ;
            #pragma unroll
            for (int m = 0; m < 4; ++m) {
                const ulonglong2 o = ((const ulonglong2*)ovS)[m];
                ull tq = 0; fma2(tq, o.x, p01); fma2(tq, o.y, p23);
                Qn[m * QSTR + i] = up2sum(tq);
            }
        }
        __syncthreads();
        cur ^= 1;
    }

    if (rowok && i >= PNP)
        *(float4*)(out + b * (NCH * MOD) + (i - PNP) * 4) =
            make_float4(pk0, pk1, pkv2, pk3);
}

extern "C" void kernel_launch(void* const* d_in, const int* in_sizes, int n_in,
                              void* d_out, int out_size) {
    const float* x        = (const float*)d_in[0];
    const float* sig_freq = (const float*)d_in[1];
    const float* sig_pow  = (const float*)d_in[2];
    const float* sig_loss = (const float*)d_in[3];
    const float* lcoef    = (const float*)d_in[4];
    const float* overlap  = (const float*)d_in[5];
    const float* raman    = (const float*)d_in[6];
    const int*   steps_p  = (const int*)d_in[10];
    const float* length_p = (const float*)d_in[11];
    const float* maxf_p   = (const float*)d_in[12];

    const int B  = in_sizes[0] / XW;
    const int Lr = in_sizes[6];

    const size_t smem =
        (size_t)(F * F + 2 * QSZ + 3 * FM + 16 + F) * sizeof(float); // 52,544 B
    cudaFuncSetAttribute(raman_kernel,
                         cudaFuncAttributeMaxDynamicSharedMemorySize, (int)smem);

    raman_kernel<<<B, NT, smem>>>(x, sig_freq, sig_pow, sig_loss, lcoef, overlap,
                                  raman, steps_p, length_p, maxf_p, Lr,
                                  (float*)d_out);
}